// round 6
// baseline (speedup 1.0000x reference)
#include <cuda_runtime.h>

// Shape fixed by the reference
#define B_    8
#define T_    4096
#define D_    1024
#define L_    8                   // timesteps per chunk
#define NC_   (T_ / L_)           // 512 chunks per chain
#define SLICES 8                  // D split into 8 slices of 128 (one warp each)
#define NCHAIN (B_ * SLICES)      // 64 independent chains
#define NITEM  (NCHAIN * NC_)     // 32768 warp-items
#define TPB   256                 // 8 warps per block
#define NBLK  (NITEM / 8)         // 4096 blocks
#define LB_W  8                   // lookback batch width

#define SMEM_BYTES (8 * 2 * L_ * 32 * 16)   // 8 warps x (a+u) x 8t x 32 lanes x 16B = 64 KB

// Decoupled-lookback state (16 MB each)
__device__ float    g_A[NITEM * 128];   // per-item aggregate: prod(a) over chunk slice
__device__ float    g_U[NITEM * 128];   // per-item aggregate: zero-carry scan tail
__device__ float    g_X[NITEM * 128];   // per-item inclusive state
__device__ unsigned g_flag[NITEM];      // 0=invalid, 1=aggregate, 2=inclusive
__device__ unsigned g_ticket;

__device__ __forceinline__ float4 f4_fma(float4 a, float4 x, float4 u) {
    float4 r;
    r.x = fmaf(a.x, x.x, u.x); r.y = fmaf(a.y, x.y, u.y);
    r.z = fmaf(a.z, x.z, u.z); r.w = fmaf(a.w, x.w, u.w);
    return r;
}
__device__ __forceinline__ float4 f4_mul(float4 a, float4 b) {
    float4 r; r.x = a.x*b.x; r.y = a.y*b.y; r.z = a.z*b.z; r.w = a.w*b.w; return r;
}
__device__ __forceinline__ unsigned ld_acq(const unsigned* p) {
    unsigned v;
    asm volatile("ld.global.acquire.gpu.b32 %0, [%1];" : "=r"(v) : "l"(p));
    return v;
}
__device__ __forceinline__ void st_rel(unsigned* p, unsigned v) {
    asm volatile("st.global.release.gpu.b32 [%0], %1;" :: "l"(p), "r"(v));
}

__global__ void k_reset() {
    int i = blockIdx.x * blockDim.x + threadIdx.x;
    if (i < NITEM) g_flag[i] = 0u;
    if (i == 0) g_ticket = 0u;
}

__global__ void __launch_bounds__(TPB, 2)
k_scan(const float* __restrict__ a,
       const float* __restrict__ u,
       const float* __restrict__ x0,
       float* __restrict__ out)
{
    extern __shared__ float4 sh[];              // per-warp private: [a: 256 f4][u: 256 f4]
    const int tid  = threadIdx.x;
    const int wid  = tid >> 5;
    const int lane = tid & 31;
    float4* sh_a = sh + wid * (2 * L_ * 32);
    float4* sh_u = sh_a + L_ * 32;

    // one ticket per warp
    unsigned vid = 0;
    if (lane == 0) vid = atomicAdd(&g_ticket, 1u);
    vid = __shfl_sync(0xffffffffu, vid, 0);

    const int chain = (int)(vid & (NCHAIN - 1));  // b*8 + slice; round-robin all chains
    const int c     = (int)(vid >> 6);
    const int b     = chain >> 3;
    const int s     = chain & 7;

    const long base = (((long)(b * T_ + c * L_) * D_) + s * 128 + lane * 4) >> 2;  // float4
    const float4* __restrict__ ap = reinterpret_cast<const float4*>(a) + base;
    const float4* __restrict__ up = reinterpret_cast<const float4*>(u) + base;

    // ---- Phase 1: stream chunk slice -> per-warp smem; aggregate on the fly
    float4 A, U;
    {
        float4 av = ap[0];
        float4 uv = up[0];
        if (c == 0) {  // fold x0 into u at global t=0
            float4 x0v = reinterpret_cast<const float4*>(x0)[b * (D_ / 4) + s * 32 + lane];
            uv = f4_fma(av, x0v, uv);
        }
        sh_a[lane] = av; sh_u[lane] = uv;
        A = av; U = uv;
        #pragma unroll
        for (int t = 1; t < L_; ++t) {
            float4 avt = ap[(long)t * (D_ / 4)];
            float4 uvt = up[(long)t * (D_ / 4)];
            sh_a[t * 32 + lane] = avt;
            sh_u[t * 32 + lane] = uvt;
            U = f4_fma(avt, U, uvt);
            A = f4_mul(A, avt);
        }
    }

    float4* gA4 = reinterpret_cast<float4*>(g_A);
    float4* gU4 = reinterpret_cast<float4*>(g_U);
    float4* gX4 = reinterpret_cast<float4*>(g_X);
    const int item = chain * NC_ + c;
    const int si   = item * 32 + lane;

    float4 x_in = make_float4(0.f, 0.f, 0.f, 0.f);

    if (c == 0) {
        gX4[si] = U;                          // inclusive known immediately
        __syncwarp();
        if (lane == 0) { __threadfence(); st_rel(&g_flag[item], 2u); }
    } else {
        gA4[si] = A;                          // publish aggregate ASAP
        gU4[si] = U;
        __syncwarp();
        if (lane == 0) { __threadfence(); st_rel(&g_flag[item], 1u); }

        // ---- Phase 2: warp-autonomous batched lookback (8 preds per round)
        float4 As = make_float4(1.f, 1.f, 1.f, 1.f);
        float4 Us = make_float4(0.f, 0.f, 0.f, 0.f);
        int p = c - 1;
        for (;;) {
            unsigned f = 0;
            const int pp = p - lane;
            if (lane < LB_W && pp >= 0) f = ld_acq(&g_flag[chain * NC_ + pp]);
            const unsigned m1 = __ballot_sync(0xffffffffu, f >= 1u) & 0xFFu;
            const unsigned m2 = __ballot_sync(0xffffffffu, f == 2u) & 0xFFu;
            const unsigned gap = (~m1) & 0xFFu;
            const int navail = gap ? (__ffs(gap) - 1) : LB_W;   // consecutive published
            const int linc   = m2 ? (__ffs(m2) - 1) : LB_W;     // first inclusive slot
            int n, inc;
            if (linc < navail) { n = linc; inc = 1; }
            else               { n = navail; inc = 0; }
            if (n == 0 && !inc) continue;                        // spin at L2 cadence
            __syncwarp();                                        // order data loads after acquire

            float4 Ab[LB_W], Ub[LB_W], Xv;
            int pi = (chain * NC_ + p) * 32 + lane;
            #pragma unroll
            for (int j = 0; j < LB_W; ++j) {
                if (j < n) { Ab[j] = gA4[pi]; Ub[j] = gU4[pi]; }
                pi -= 32;
            }
            if (inc) Xv = gX4[(chain * NC_ + (p - n)) * 32 + lane];

            #pragma unroll
            for (int j = 0; j < LB_W; ++j) {
                if (j < n) { Us = f4_fma(As, Ub[j], Us); As = f4_mul(As, Ab[j]); }
            }
            if (inc) { x_in = f4_fma(As, Xv, Us); break; }
            p -= n;
        }

        // ---- Phase 3: publish inclusive (unblocks successors before phase 4)
        gX4[si] = f4_fma(A, x_in, U);
        __syncwarp();
        if (lane == 0) { __threadfence(); st_rel(&g_flag[item], 2u); }
    }

    // ---- Phase 4: replay slice from per-warp smem, write outputs
    float4* __restrict__ op = reinterpret_cast<float4*>(out) + base;
    float4 x = x_in;
    #pragma unroll
    for (int t = 0; t < L_; ++t) {
        float4 av = sh_a[t * 32 + lane];
        float4 uv = sh_u[t * 32 + lane];
        x = f4_fma(av, x, uv);
        op[(long)t * (D_ / 4)] = x;
    }
}

extern "C" void kernel_launch(void* const* d_in, const int* in_sizes, int n_in,
                              void* d_out, int out_size) {
    const float* x0 = (const float*)d_in[0];
    const float* a  = (const float*)d_in[1];
    const float* u  = (const float*)d_in[2];
    float* out = (float*)d_out;

    cudaFuncSetAttribute(k_scan, cudaFuncAttributeMaxDynamicSharedMemorySize, SMEM_BYTES);

    k_reset<<<(NITEM + 255) / 256, 256>>>();
    k_scan<<<NBLK, TPB, SMEM_BYTES>>>(a, u, x0, out);
}